// round 2
// baseline (speedup 1.0000x reference)
#include <cuda_runtime.h>
#include <cuda_bf16.h>

// RBFSetConv separable reformulation:
//   w(n,(gx,gy)) = exp(-50*(x-gx)^2) * exp(-50*(y-gy)^2)  (sigma=0.1)
//   density[b,gy,gx]   = sum_n wx[n,gx]*wy[n,gy]
//   wsum_c[b,gy,gx]    = sum_n f_c[n]*wx[n,gx]*wy[n,gy]
// => per batch: C = A^T @ B,  A:(N,192) = [wx | y*wx | t*wx], B:(N,64) = wy
// Output out[b,0]=density, out[b,1..2]=wsum/(density+1e-5), index g = gy*64+gx.

#define B_     8
#define N_     4096
#define GR     64
#define NROWS  192            // 3 channels * 64 gx
#define SPLITS 37             // 8*37 = 296 CTAs = 2 per SM on 148 SMs
#define CTAS   (B_ * SPLITS)
#define CHUNK  16
#define NCHUNKS (N_ / CHUNK)  // 256

__device__ float g_accum[B_ * NROWS * GR];
__device__ int   g_mask_mode;

__device__ __forceinline__ float ex2f(float x) {
    float r;
    asm("ex2.approx.ftz.f32 %0, %1;" : "=f"(r) : "f"(x));
    return r;
}

// Packed f32x2 FMA (Blackwell): acc.lo += a.lo*b.lo; acc.hi += a.hi*b.hi
__device__ __forceinline__ void ffma2(unsigned long long& d,
                                      unsigned long long a,
                                      unsigned long long b) {
    asm("fma.rn.f32x2 %0, %1, %2, %0;" : "+l"(d) : "l"(a), "l"(b));
}

__device__ __forceinline__ unsigned long long pack2(float x) {
    unsigned long long r;
    asm("mov.b64 %0, {%1, %1};" : "=l"(r) : "f"(x));
    return r;
}

// Kernel 0: zero accumulator scratch + detect mask dtype encoding.
// Reads at most 32768 bytes of the mask buffer (minimum possible size).
__global__ void k_init(const void* mask) {
    int stride = gridDim.x * blockDim.x;
    for (int i = blockIdx.x * blockDim.x + threadIdx.x; i < B_ * NROWS * GR; i += stride)
        g_accum[i] = 0.0f;

    if (blockIdx.x == 0) {
        __shared__ int bad[3];
        if (threadIdx.x < 3) bad[threadIdx.x] = 0;
        __syncthreads();
        int bi = 0, bf = 0, bh = 0;
        const unsigned*       iv = (const unsigned*)mask;
        const float*          fv = (const float*)mask;
        const unsigned short* hv = (const unsigned short*)mask;
        for (int n = threadIdx.x; n < 8192; n += blockDim.x) {
            unsigned u = iv[n];
            if (u > 1u) bi = 1;
            float f = fv[n];
            if (!(f == 0.0f || f == 1.0f)) bf = 1;
        }
        for (int n = threadIdx.x; n < 16384; n += blockDim.x) {
            unsigned short h = hv[n];
            if (h != 0 && h != 0x3F80) bh = 1;
        }
        if (bi) atomicOr(&bad[0], 1);
        if (bf) atomicOr(&bad[1], 1);
        if (bh) atomicOr(&bad[2], 1);
        __syncthreads();
        if (threadIdx.x == 0) {
            g_mask_mode = (!bad[0]) ? 0 : (!bad[1]) ? 1 : (!bad[2]) ? 2 : 3;
        }
    }
}

// Main kernel: per (batch, split) CTA, accumulate 192x64 partial C over its
// point chunks. 256 threads: 32 row-threads x 6 rows, 8 col-threads x 8 cols.
__global__ void __launch_bounds__(256, 2)
k_main(const float* __restrict__ xc, const float* __restrict__ yc,
       const float* __restrict__ tc, const void* __restrict__ mask) {
    __shared__ float sA[CHUNK][NROWS];
    __shared__ float sB[CHUNK][GR];

    const int b   = blockIdx.x / SPLITS;
    const int s   = blockIdx.x % SPLITS;
    const int tid = threadIdx.x;
    const int mode = g_mask_mode;

    const int row_t = tid >> 3;  // 0..31
    const int col_t = tid & 7;   // 0..7
    const int p     = tid >> 4;  // 0..15 (point within chunk for prep)
    const int q     = tid & 15;  // 0..15 (4 grid columns each)

    unsigned long long acc[6][4];
#pragma unroll
    for (int r = 0; r < 6; r++)
#pragma unroll
        for (int c = 0; c < 4; c++) acc[r][c] = 0ull;

    for (int ci = s; ci < NCHUNKS; ci += SPLITS) {
        // ---- prep: build A (wx, y*wx, t*wx) and B (wy) tiles in smem ----
        const int n  = ci * CHUNK + p;
        const int gi = b * N_ + n;
        float2 pt = ((const float2*)xc)[gi];
        float yv = yc[gi];
        float tv = tc[gi];
        bool m;
        if (mode == 0)      m = ((const int*)mask)[gi] != 0;
        else if (mode == 1) m = ((const float*)mask)[gi] != 0.0f;
        else if (mode == 2) m = (((const unsigned short*)mask)[gi] & 0x7FFF) != 0;
        else                m = ((const unsigned char*)mask)[gi] != 0;
        const float vm = m ? 0.0f : 1.0f;

        float wx[4], wy[4];
#pragma unroll
        for (int k = 0; k < 4; k++) {
            float c  = -1.0f + (float)(q * 4 + k) * (2.0f / 63.0f);
            float dx = pt.x - c;
            float dy = pt.y - c;
            // -0.5/sigma^2 * log2(e) = -50 * 1.44269504 = -72.134752
            wx[k] = ex2f(-72.134752f * dx * dx) * vm;
            wy[k] = ex2f(-72.134752f * dy * dy);
        }
        *(float4*)&sB[p][q * 4]       = make_float4(wy[0], wy[1], wy[2], wy[3]);
        *(float4*)&sA[p][q * 4]       = make_float4(wx[0], wx[1], wx[2], wx[3]);
        *(float4*)&sA[p][64 + q * 4]  = make_float4(yv * wx[0], yv * wx[1], yv * wx[2], yv * wx[3]);
        *(float4*)&sA[p][128 + q * 4] = make_float4(tv * wx[0], tv * wx[1], tv * wx[2], tv * wx[3]);
        __syncthreads();

        // ---- accumulate: rank-16 update of the 192x64 tile (FFMA2) ----
#pragma unroll
        for (int pp = 0; pp < CHUNK; pp++) {
            const unsigned long long* bp =
                (const unsigned long long*)&sB[pp][col_t * 8];
            unsigned long long b0 = bp[0], b1 = bp[1], b2 = bp[2], b3 = bp[3];
            const float* ap = &sA[pp][row_t];
#pragma unroll
            for (int rr = 0; rr < 6; rr++) {
                unsigned long long av = pack2(ap[rr * 32]);
                ffma2(acc[rr][0], av, b0);
                ffma2(acc[rr][1], av, b1);
                ffma2(acc[rr][2], av, b2);
                ffma2(acc[rr][3], av, b3);
            }
        }
        __syncthreads();
    }

    // ---- flush partial C into global accumulator ----
    float* dst = &g_accum[b * NROWS * GR];
#pragma unroll
    for (int rr = 0; rr < 6; rr++) {
        const int row = row_t + 32 * rr;
#pragma unroll
        for (int c = 0; c < 4; c++) {
            unsigned long long v = acc[rr][c];
            const int col = col_t * 8 + c * 2;
            atomicAdd(&dst[row * GR + col],     __uint_as_float((unsigned)v));
            atomicAdd(&dst[row * GR + col + 1], __uint_as_float((unsigned)(v >> 32)));
        }
    }
}

// Finalize: out[b,0,i,j]=den, out[b,1..2,i,j]=sum/(den+eps)
// C layout: row = c*64 + gx(=j), col = gy(=i)
__global__ void k_fin(float* __restrict__ out) {
    int idx = blockIdx.x * blockDim.x + threadIdx.x;
    if (idx >= B_ * GR * GR) return;
    int b  = idx >> 12;
    int ij = idx & 4095;
    int i  = ij >> 6;
    int j  = ij & 63;
    const float* acc = &g_accum[b * NROWS * GR];
    float den = acc[j * GR + i];
    float s1  = acc[(64 + j) * GR + i];
    float s2  = acc[(128 + j) * GR + i];
    float inv = 1.0f / (den + 1e-5f);
    float* o = out + b * 3 * 4096 + ij;
    o[0]    = den;
    o[4096] = s1 * inv;
    o[8192] = s2 * inv;
}

extern "C" void kernel_launch(void* const* d_in, const int* in_sizes, int n_in,
                              void* d_out, int out_size) {
    const float* xc   = (const float*)d_in[0];
    const float* yc   = (const float*)d_in[1];
    const float* tc   = (const float*)d_in[2];
    const void*  mask = d_in[3];

    k_init<<<128, 256>>>(mask);
    k_main<<<CTAS, 256>>>(xc, yc, tc, mask);
    k_fin<<<128, 256>>>((float*)d_out);
}

// round 4
// speedup vs baseline: 1.3155x; 1.3155x over previous
#include <cuda_runtime.h>
#include <cuda_bf16.h>

// RBFSetConv separable reformulation:
//   w(n,(gx,gy)) = exp(-50*(x-gx)^2) * exp(-50*(y-gy)^2)   (sigma = 0.1)
// Per batch: C(192x64) = A^T(192x4096) @ B(4096x64),
//   A = [wx | y*wx | t*wx] (mask folded into wx), B = wy.
// Split-K over 37 CTAs/batch -> private partial tiles (no atomics),
// k_fin reduces partials and finalizes density / normalized sums.
//
// wx/wy computed by 2nd-order multiplicative recurrence (3 ex2 per 16-col
// segment instead of 16): w_{k+1} = w_k * r_k, r_{k+1} = r_k * q, marching
// outward from the nearest grid index (monotone decreasing -> underflow-safe).

#define B_      8
#define N_      4096
#define GR      64
#define SPLITS  37
#define CTAS    (B_ * SPLITS)        // 296 = 2 CTAs per SM
#define CHUNK   32
#define NCHUNKS (N_ / CHUNK)         // 128

#define APITCH  194                  // u64 elements per point-row of A
#define BPITCH  288                  // bytes per point-row of B (skewed)
#define AOFF    0
#define BOFF    (CHUNK * APITCH * 8) // 49664
#define SMEM_BYTES (BOFF + CHUNK * BPITCH)  // 58880

#define DEL     0.031746032f         // 2/63
#define ALG     72.134752f           // 50 * log2(e)
#define C1C     4.579985f            // 2*50*DEL*log2(e)
#define C2C     (-0.0727013f)        // -50*DEL*DEL*log2(e)
#define QF      0.90413095f          // exp(-2*50*DEL*DEL)

__device__ float g_part[CTAS * 192 * GR];   // per-CTA partial tiles (14.5 MB)

typedef unsigned long long ull;

__device__ __forceinline__ float ex2f(float x) {
    float r; asm("ex2.approx.ftz.f32 %0, %1;" : "=f"(r) : "f"(x)); return r;
}
__device__ __forceinline__ void ffma2(ull& d, ull a, ull b) {
    asm("fma.rn.f32x2 %0, %1, %2, %0;" : "+l"(d) : "l"(a), "l"(b));
}
// store {v, v} as one 8B shared store (pre-duplicated A operand)
__device__ __forceinline__ void sts_dup(unsigned a, float v) {
    asm volatile("st.shared.v2.f32 [%0], {%1, %1};" :: "r"(a), "f"(v));
}
__device__ __forceinline__ void sts_f32(unsigned a, float v) {
    asm volatile("st.shared.f32 [%0], %1;" :: "r"(a), "f"(v));
}

// bitwise-exact classification of one int against the 4 candidate encodings
__device__ __forceinline__ void chk1(unsigned v, int& bi, int& bf, int& bh) {
    bi |= (v > 1u);
    bf |= (v != 0u && v != 0x3F800000u);
    unsigned lo = v & 0xFFFFu, hi = v >> 16;
    bh |= (lo != 0u && lo != 0x3F80u) || (hi != 0u && hi != 0x3F80u);
}

__global__ void __launch_bounds__(256, 2)
k_main(const float* __restrict__ xc, const float* __restrict__ yc,
       const float* __restrict__ tc, const void* __restrict__ mask) {
    extern __shared__ __align__(16) char smem[];
    __shared__ int smode;

    const int tid = threadIdx.x;
    const int b   = blockIdx.x / SPLITS;
    const int s   = blockIdx.x % SPLITS;

    // ---- per-CTA mask dtype detection (bitwise, 1KB sample, warp 0) ----
    if (tid < 32) {
        const int4* mv = (const int4*)mask;
        int4 a = __ldg(mv + tid);
        int4 c = __ldg(mv + tid + 32);
        int bi = 0, bf = 0, bh = 0;
        chk1((unsigned)a.x, bi, bf, bh); chk1((unsigned)a.y, bi, bf, bh);
        chk1((unsigned)a.z, bi, bf, bh); chk1((unsigned)a.w, bi, bf, bh);
        chk1((unsigned)c.x, bi, bf, bh); chk1((unsigned)c.y, bi, bf, bh);
        chk1((unsigned)c.z, bi, bf, bh); chk1((unsigned)c.w, bi, bf, bh);
        bi = __any_sync(0xFFFFFFFFu, bi);
        bf = __any_sync(0xFFFFFFFFu, bf);
        bh = __any_sync(0xFFFFFFFFu, bh);
        if (tid == 0) smode = (!bi) ? 0 : (!bf) ? 1 : (!bh) ? 2 : 3;
    }
    __syncthreads();
    const int mode = smode;

    const unsigned sbase = (unsigned)__cvta_generic_to_shared(smem);

    // GEMM tiling: 32 row-threads x 6 rows, 8 col-threads x 8 cols
    const int row_t = tid >> 3;   // 0..31
    const int col_t = tid & 7;    // 0..7

    // prep tasks: threads 0-127 -> wx (3 channels), 128-255 -> wy.
    // task = (point p, quarter qh): 16 grid columns [16*qh, 16*qh+16)
    const bool is_wx = (tid < 128);
    const int  tt = is_wx ? tid : tid - 128;
    const int  p  = tt >> 2;
    const int  qh = tt & 3;
    const int  lo = qh * 16, hi = lo + 15;

    ull acc[6][4];
#pragma unroll
    for (int r = 0; r < 6; r++)
#pragma unroll
        for (int c = 0; c < 4; c++) acc[r][c] = 0ull;

    for (int ci = s; ci < NCHUNKS; ci += SPLITS) {
        // ---------------- prep: build A (dup u64) and B (skewed) ----------
        {
            const int gi = b * N_ + ci * CHUNK + p;
            float2 pt = ((const float2*)xc)[gi];
            float x = is_wx ? pt.x : pt.y;

            float fi = (x + 1.0f) * 31.5f;
            int kc = __float2int_rn(fi);
            kc = min(max(kc, lo), hi);
            float d  = x - (-1.0f + (float)kc * DEL);
            float w0 = ex2f(-ALG * d * d);
            float rup = ex2f( C1C * d + C2C);
            float rdn = ex2f(-C1C * d + C2C);

            if (is_wx) {
                float yv = yc[gi], tv = tc[gi];
                float vm;
                if (mode == 0)      vm = (((const int*)mask)[gi] != 0) ? 0.0f : 1.0f;
                else if (mode == 1) vm = (((const unsigned*)mask)[gi] != 0u) ? 0.0f : 1.0f;
                else if (mode == 2) vm = ((((const unsigned short*)mask)[gi]) != 0) ? 0.0f : 1.0f;
                else                vm = (((const unsigned char*)mask)[gi] != 0) ? 0.0f : 1.0f;
                w0 *= vm;

                const unsigned a0 = sbase + (unsigned)(p * APITCH) * 8u;
                float w = w0, r = rup;
#pragma unroll
                for (int j = 0; j < 16; j++) {
                    int k = kc + j;
                    if (k <= hi) {
                        unsigned ad = a0 + (unsigned)k * 8u;
                        sts_dup(ad,          w);
                        sts_dup(ad + 512u,   yv * w);   //  64*8
                        sts_dup(ad + 1024u,  tv * w);   // 128*8
                    }
                    w *= r; r *= QF;
                }
                w = w0; r = rdn;
#pragma unroll
                for (int j = 1; j < 16; j++) {
                    w *= r; r *= QF;
                    int k = kc - j;
                    if (k >= lo) {
                        unsigned ad = a0 + (unsigned)k * 8u;
                        sts_dup(ad,          w);
                        sts_dup(ad + 512u,   yv * w);
                        sts_dup(ad + 1024u,  tv * w);
                    }
                }
            } else {
                const unsigned b0a = sbase + (unsigned)BOFF + (unsigned)(p * BPITCH);
                float w = w0, r = rup;
#pragma unroll
                for (int j = 0; j < 16; j++) {
                    int k = kc + j;
                    if (k <= hi)
                        sts_f32(b0a + (unsigned)(k * 4 + ((k >> 4) << 3)), w);
                    w *= r; r *= QF;
                }
                w = w0; r = rdn;
#pragma unroll
                for (int j = 1; j < 16; j++) {
                    w *= r; r *= QF;
                    int k = kc - j;
                    if (k >= lo)
                        sts_f32(b0a + (unsigned)(k * 4 + ((k >> 4) << 3)), w);
                }
            }
        }
        __syncthreads();

        // ---------------- rank-32 FFMA2 update of the 192x64 tile ---------
        const ull* __restrict__ Ad = (const ull*)smem;
        const char* __restrict__ Bb = smem + BOFF + col_t * 32 + ((col_t >> 1) << 3);
#pragma unroll 4
        for (int pp = 0; pp < CHUNK; pp++) {
            const char* bb = Bb + pp * BPITCH;
            ull b0 = *(const ull*)(bb);
            ull b1 = *(const ull*)(bb + 8);
            ull b2 = *(const ull*)(bb + 16);
            ull b3 = *(const ull*)(bb + 24);
            const ull* ap = Ad + pp * APITCH + row_t;
#pragma unroll
            for (int rr = 0; rr < 6; rr++) {
                ull av = ap[rr * 32];
                ffma2(acc[rr][0], av, b0);
                ffma2(acc[rr][1], av, b1);
                ffma2(acc[rr][2], av, b2);
                ffma2(acc[rr][3], av, b3);
            }
        }
        __syncthreads();
    }

    // ---------------- flush private partial tile (plain STG.64) -----------
    ull* pu = (ull*)(g_part + (size_t)blockIdx.x * (192 * GR));
#pragma unroll
    for (int rr = 0; rr < 6; rr++) {
        const int row = row_t + 32 * rr;
#pragma unroll
        for (int c = 0; c < 4; c++)
            pu[row * 32 + col_t * 4 + c] = acc[rr][c];
    }
}

// Reduce 37 partials per batch, finalize. C layout: row = ch*64 + gx(=j), col = gy(=i).
__global__ void k_fin(float* __restrict__ out) {
    int idx = blockIdx.x * blockDim.x + threadIdx.x;   // b, j, i (i fastest)
    int b   = idx >> 12;
    int rem = idx & 4095;
    int j   = rem >> 6;
    int i   = rem & 63;

    const float* base = g_part + (size_t)b * SPLITS * (192 * GR);
    float den = 0.0f, s1 = 0.0f, s2 = 0.0f;
#pragma unroll
    for (int s = 0; s < SPLITS; s++) {
        const float* t = base + s * (192 * GR);
        den += __ldg(t + j * GR + i);
        s1  += __ldg(t + (64 + j) * GR + i);
        s2  += __ldg(t + (128 + j) * GR + i);
    }
    float inv = 1.0f / (den + 1e-5f);
    float* o = out + b * 3 * 4096 + i * GR + j;
    o[0]    = den;
    o[4096] = s1 * inv;
    o[8192] = s2 * inv;
}

extern "C" void kernel_launch(void* const* d_in, const int* in_sizes, int n_in,
                              void* d_out, int out_size) {
    const float* xc   = (const float*)d_in[0];
    const float* yc   = (const float*)d_in[1];
    const float* tc   = (const float*)d_in[2];
    const void*  mask = d_in[3];

    static int smem_set = 0;
    if (!smem_set) {
        cudaFuncSetAttribute(k_main, cudaFuncAttributeMaxDynamicSharedMemorySize,
                             SMEM_BYTES);
        smem_set = 1;
    }
    k_main<<<CTAS, 256, SMEM_BYTES>>>(xc, yc, tc, mask);
    k_fin<<<128, 256>>>((float*)d_out);
}